// round 8
// baseline (speedup 1.0000x reference)
#include <cuda_runtime.h>
#include <cuda_bf16.h>
#include <cuda_fp16.h>
#include <math.h>

#define NN 100000
#define NN_PAD 100096            // 782 * 128
#define NE 3200000
#define NG 128
#define H  128

// ---------------- scratch (device globals; zero-initialized, no allocation) -----
__device__ int      g_csr[NE];
__device__ int      g_rank[NE];
__device__ int      g_off[NN + 1];
__device__ int      g_deg[NN];          // zero at entry (module-load / classifier tail)
__device__ int      g_bsum[128];
__device__ int      g_batch[NN];
__device__ int      g_cnt[NG];          // zero at entry
__device__ float    g_dinv[NN_PAD];     // pad rows stay 0
__device__ unsigned g_hb[(size_t)NN_PAD * 64];   // h in bf16 (64 uints = 128 bf16/row)
__device__ unsigned g_m8[(size_t)NN_PAD * 32];   // m in fp8 e4m3 (32 uints = 128 fp8/row)
__device__ float    g_pool[NG * H];     // zero at entry
__device__ float    g_u[H];
__device__ float    g_v[H];

// Deterministic dtype probe: 4 leading values read as int64 all being valid node
// ids implies int64 layout.
__device__ __forceinline__ bool idx_is64(const void* p) {
    const long long* q = (const long long*)p;
    bool ok = true;
#pragma unroll
    for (int i = 0; i < 4; i++) {
        long long v = q[i];
        if (v < 0 || v >= NN) ok = false;
    }
    return ok;
}

// ---------------- fp8 helpers ----------------
__device__ __forceinline__ __half2 fp8x2_to_h2(unsigned short s) {
    unsigned r;
    asm("cvt.rn.f16x2.e4m3x2 %0, %1;" : "=r"(r) : "h"(s));
    return *(__half2*)&r;
}
__device__ __forceinline__ unsigned short f2_to_fp8x2(float lo, float hi) {
    unsigned short r;
    asm("cvt.rn.satfinite.e4m3x2.f32 %0, %1, %2;" : "=h"(r) : "f"(hi), "f"(lo));
    return r;
}
__device__ __forceinline__ unsigned pack4_fp8(float f0, float f1, float f2, float f3) {
    unsigned lo = f2_to_fp8x2(f0, f1);
    unsigned hi = f2_to_fp8x2(f2, f3);
    return lo | (hi << 16);
}

// ---------------- preprocessing ----------------
// histogram + per-edge rank; 4 edges/thread, vectorized loads, MLP=4 atomic chains
__global__ void k_conv_edges(const void* ei) {
    bool is64 = idx_is64(ei);
    int idx = blockIdx.x * blockDim.x + threadIdx.x;   // NE/4 threads exactly
    int4 c4;
    if (is64) {
        const longlong2* p = (const longlong2*)ei;
        longlong2 c01 = __ldg(p + NE / 2 + (size_t)idx * 2);
        longlong2 c23 = __ldg(p + NE / 2 + (size_t)idx * 2 + 1);
        c4 = make_int4((int)c01.x, (int)c01.y, (int)c23.x, (int)c23.y);
    } else {
        c4 = __ldg(((const int4*)ei) + NE / 4 + idx);
    }
    int4 rk;
    rk.x = atomicAdd(&g_deg[c4.x], 1);
    rk.y = atomicAdd(&g_deg[c4.y], 1);
    rk.z = atomicAdd(&g_deg[c4.z], 1);
    rk.w = atomicAdd(&g_deg[c4.w], 1);
    ((int4*)g_rank)[idx] = rk;
}

__global__ void k_conv_batch(const void* b, const void* ei) {
    bool is64 = idx_is64(ei);
    int idx = blockIdx.x * blockDim.x + threadIdx.x;
    if (idx * 4 >= NN) return;
    int g0, g1, g2, g3;
    if (is64) {
        const longlong2* p = (const longlong2*)b;
        longlong2 a = __ldg(p + (size_t)idx * 2), c = __ldg(p + (size_t)idx * 2 + 1);
        g0 = (int)a.x; g1 = (int)a.y; g2 = (int)c.x; g3 = (int)c.y;
    } else {
        int4 a = __ldg(((const int4*)b) + idx);
        g0 = a.x; g1 = a.y; g2 = a.z; g3 = a.w;
    }
    ((int4*)g_batch)[idx] = make_int4(g0, g1, g2, g3);
    atomicAdd(&g_cnt[g0], 1);
    atomicAdd(&g_cnt[g1], 1);
    atomicAdd(&g_cnt[g2], 1);
    atomicAdd(&g_cnt[g3], 1);
}

__global__ void k_scan1() {
    __shared__ int s[1024];
    int t = threadIdx.x, gid = blockIdx.x * 1024 + t;
    int v = (gid < NN) ? g_deg[gid] : 0;
    s[t] = v; __syncthreads();
    for (int d = 1; d < 1024; d <<= 1) {
        int x = (t >= d) ? s[t - d] : 0;
        __syncthreads();
        s[t] += x; __syncthreads();
    }
    if (gid < NN) g_off[gid] = s[t] - v;
    if (t == 1023) g_bsum[blockIdx.x] = s[1023];
}

// adds block-prefix + fused dinv
__global__ void k_scan3() {
    __shared__ int s[128];
    int t = threadIdx.x, nb = blockIdx.x;
    if (t < 128) s[t] = (t < nb) ? g_bsum[t] : 0;
    __syncthreads();
    for (int d = 64; d > 0; d >>= 1) {
        if (t < d) s[t] += s[t + d];
        __syncthreads();
    }
    int base = s[0];
    int gid = nb * 1024 + t;
    if (gid < NN) {
        g_off[gid] += base;
        g_dinv[gid] = rsqrtf((float)(1 + g_deg[gid]));
    }
    if (nb == 0 && t == 0) g_off[NN] = NE;
}

// atomic-free CSR fill, 4 edges/thread: pos = off[col] + rank
__global__ void k_scatter(const void* ei) {
    bool is64 = idx_is64(ei);
    int idx = blockIdx.x * blockDim.x + threadIdx.x;   // NE/4 threads exactly
    int4 r4, c4;
    if (is64) {
        const longlong2* p = (const longlong2*)ei;
        longlong2 r01 = __ldg(p + (size_t)idx * 2);
        longlong2 r23 = __ldg(p + (size_t)idx * 2 + 1);
        longlong2 c01 = __ldg(p + NE / 2 + (size_t)idx * 2);
        longlong2 c23 = __ldg(p + NE / 2 + (size_t)idx * 2 + 1);
        r4 = make_int4((int)r01.x, (int)r01.y, (int)r23.x, (int)r23.y);
        c4 = make_int4((int)c01.x, (int)c01.y, (int)c23.x, (int)c23.y);
    } else {
        r4 = __ldg(((const int4*)ei) + idx);
        c4 = __ldg(((const int4*)ei) + NE / 4 + idx);
    }
    int4 rk = ((const int4*)g_rank)[idx];
    g_csr[__ldg(g_off + c4.x) + rk.x] = r4.x;
    g_csr[__ldg(g_off + c4.y) + rk.y] = r4.y;
    g_csr[__ldg(g_off + c4.z) + rk.z] = r4.z;
    g_csr[__ldg(g_off + c4.w) + rk.w] = r4.w;
}

// u = W_emb @ W0, v = b_emb @ W0
__global__ void k_uv(const float* __restrict__ We, const float* __restrict__ be,
                     const float* __restrict__ W0) {
    int j = threadIdx.x;
    float u = 0.f, v = 0.f;
#pragma unroll 4
    for (int k = 0; k < 128; k++) {
        float w = W0[k * 128 + j];
        u = fmaf(We[k], w, u);
        v = fmaf(be[k], w, v);
    }
    g_u[j] = u; g_v[j] = v;
}

// m0[n] = dinv[n] * (x[n]*u + v), stored fp8
__global__ void k_m0(const float* __restrict__ x) {
    int i = blockIdx.x * blockDim.x + threadIdx.x;   // NN*32 threads
    int n = i >> 5, j4 = i & 31;
    float xv = __ldg(&x[n]);
    float d = g_dinv[n];
    float4 u = ((const float4*)g_u)[j4];
    float4 v = ((const float4*)g_v)[j4];
    g_m8[(size_t)n * 32 + j4] = pack4_fp8(
        d * fmaf(xv, u.x, v.x), d * fmaf(xv, u.y, v.y),
        d * fmaf(xv, u.z, v.z), d * fmaf(xv, u.w, v.w));
}

// ---------------- bf16 tensor-core GEMM: m = dinv ⊙ (h @ W), fp8 out ----------
#define AST 68
__global__ void __launch_bounds__(256, 2) k_gemm(const float* __restrict__ Wl) {
    extern __shared__ unsigned smem_u[];
    unsigned* hs  = smem_u;                          // 128*68 uints
    uint2*    WtP = (uint2*)(smem_u + 128 * AST);    // 128*32 uint2
    int t = threadIdx.x;
    int row0 = blockIdx.x * 128;

    {
        const uint4* src = (const uint4*)(g_hb + (size_t)row0 * 64);
        for (int idx = t; idx < 128 * 16; idx += 256) {
            int r = idx >> 4, c = idx & 15;
            *(uint4*)(hs + r * AST + c * 4) = src[r * 16 + c];
        }
    }
    for (int idx = t; idx < 32 * 128; idx += 256) {
        int j = idx >> 7, n = idx & 127;
        int ks = j >> 2, tt = j & 3;
        int kp0 = ks * 8 + tt, kp1 = kp0 + 4;
        __nv_bfloat162 p0 = __floats2bfloat162_rn(Wl[(2 * kp0) * 128 + n],
                                                  Wl[(2 * kp0 + 1) * 128 + n]);
        __nv_bfloat162 p1 = __floats2bfloat162_rn(Wl[(2 * kp1) * 128 + n],
                                                  Wl[(2 * kp1 + 1) * 128 + n]);
        uint2 o; o.x = *(unsigned*)&p0; o.y = *(unsigned*)&p1;
        WtP[n * 32 + ((j + 4 * (n & 3)) & 31)] = o;
    }
    __syncthreads();

    int w = t >> 5, lane = t & 31, g = lane >> 2, tt = lane & 3;
    int wr = w * 16;

    float c[16][4];
#pragma unroll
    for (int nt = 0; nt < 16; nt++)
        c[nt][0] = c[nt][1] = c[nt][2] = c[nt][3] = 0.f;

#pragma unroll
    for (int ks = 0; ks < 8; ks++) {
        int kb = ks * 8;
        unsigned a0 = hs[(wr + g) * AST + kb + tt];
        unsigned a1 = hs[(wr + g + 8) * AST + kb + tt];
        unsigned a2 = hs[(wr + g) * AST + kb + tt + 4];
        unsigned a3 = hs[(wr + g + 8) * AST + kb + tt + 4];
#pragma unroll
        for (int nt = 0; nt < 16; nt++) {
            int n = nt * 8 + g;
            uint2 b01 = WtP[n * 32 + (((ks * 4 + tt) + 4 * (n & 3)) & 31)];
            asm volatile(
                "mma.sync.aligned.m16n8k16.row.col.f32.bf16.bf16.f32 "
                "{%0,%1,%2,%3}, {%4,%5,%6,%7}, {%8,%9}, {%0,%1,%2,%3};"
                : "+f"(c[nt][0]), "+f"(c[nt][1]), "+f"(c[nt][2]), "+f"(c[nt][3])
                : "r"(a0), "r"(a1), "r"(a2), "r"(a3), "r"(b01.x), "r"(b01.y));
        }
    }

    int r0 = row0 + wr + g, r1 = r0 + 8;
    float d0 = g_dinv[r0], d1 = g_dinv[r1];
    unsigned short* m8s = (unsigned short*)g_m8;     // row = 64 ushorts
#pragma unroll
    for (int nt = 0; nt < 16; nt++) {
        int colp = nt * 4 + tt;
        m8s[(size_t)r0 * 64 + colp] = f2_to_fp8x2(c[nt][0] * d0, c[nt][1] * d0);
        m8s[(size_t)r1 * 64 + colp] = f2_to_fp8x2(c[nt][2] * d1, c[nt][3] * d1);
    }
}

// ---------------- aggregation: warp per node, fp8 gathers, 8-wide MLP ----------
// __ldcg: bypass L1 (12.8MB working set is L1-useless, L2-resident)
__device__ __forceinline__ unsigned ldcg_u(const unsigned* p) { return __ldcg(p); }

__global__ void k_agg(const float* __restrict__ bias, int last) {
    unsigned n = (blockIdx.x * blockDim.x + threadIdx.x) >> 5;
    if (n >= NN) return;
    int lane = threadIdx.x & 31;
    const unsigned* m8 = g_m8;                       // row = 32 uints = 128 fp8
    __half2 aA[4], aB[4];
#pragma unroll
    for (int j = 0; j < 4; j++) { aA[j] = __half2half2(__ushort_as_half(0)); aB[j] = aA[j]; }
    {
        unsigned v = ldcg_u(m8 + (size_t)n * 32 + lane);   // self-loop
        aA[0] = fp8x2_to_h2((unsigned short)v);
        aB[0] = fp8x2_to_h2((unsigned short)(v >> 16));
    }
    int s = g_off[n], e = g_off[n + 1];
    int i = s;
    for (; i + 8 <= e; i += 8) {
        int r0 = __ldcs(g_csr + i),     r1 = __ldcs(g_csr + i + 1);
        int r2 = __ldcs(g_csr + i + 2), r3 = __ldcs(g_csr + i + 3);
        int r4 = __ldcs(g_csr + i + 4), r5 = __ldcs(g_csr + i + 5);
        int r6 = __ldcs(g_csr + i + 6), r7 = __ldcs(g_csr + i + 7);
        unsigned v0 = ldcg_u(m8 + (size_t)r0 * 32 + lane);
        unsigned v1 = ldcg_u(m8 + (size_t)r1 * 32 + lane);
        unsigned v2 = ldcg_u(m8 + (size_t)r2 * 32 + lane);
        unsigned v3 = ldcg_u(m8 + (size_t)r3 * 32 + lane);
        unsigned v4 = ldcg_u(m8 + (size_t)r4 * 32 + lane);
        unsigned v5 = ldcg_u(m8 + (size_t)r5 * 32 + lane);
        unsigned v6 = ldcg_u(m8 + (size_t)r6 * 32 + lane);
        unsigned v7 = ldcg_u(m8 + (size_t)r7 * 32 + lane);
        aA[0] = __hadd2(aA[0], fp8x2_to_h2((unsigned short)v0));
        aB[0] = __hadd2(aB[0], fp8x2_to_h2((unsigned short)(v0 >> 16)));
        aA[1] = __hadd2(aA[1], fp8x2_to_h2((unsigned short)v1));
        aB[1] = __hadd2(aB[1], fp8x2_to_h2((unsigned short)(v1 >> 16)));
        aA[2] = __hadd2(aA[2], fp8x2_to_h2((unsigned short)v2));
        aB[2] = __hadd2(aB[2], fp8x2_to_h2((unsigned short)(v2 >> 16)));
        aA[3] = __hadd2(aA[3], fp8x2_to_h2((unsigned short)v3));
        aB[3] = __hadd2(aB[3], fp8x2_to_h2((unsigned short)(v3 >> 16)));
        aA[0] = __hadd2(aA[0], fp8x2_to_h2((unsigned short)v4));
        aB[0] = __hadd2(aB[0], fp8x2_to_h2((unsigned short)(v4 >> 16)));
        aA[1] = __hadd2(aA[1], fp8x2_to_h2((unsigned short)v5));
        aB[1] = __hadd2(aB[1], fp8x2_to_h2((unsigned short)(v5 >> 16)));
        aA[2] = __hadd2(aA[2], fp8x2_to_h2((unsigned short)v6));
        aB[2] = __hadd2(aB[2], fp8x2_to_h2((unsigned short)(v6 >> 16)));
        aA[3] = __hadd2(aA[3], fp8x2_to_h2((unsigned short)v7));
        aB[3] = __hadd2(aB[3], fp8x2_to_h2((unsigned short)(v7 >> 16)));
    }
    for (; i < e; i++) {
        int r = __ldcs(g_csr + i);
        unsigned v = ldcg_u(m8 + (size_t)r * 32 + lane);
        aA[0] = __hadd2(aA[0], fp8x2_to_h2((unsigned short)v));
        aB[0] = __hadd2(aB[0], fp8x2_to_h2((unsigned short)(v >> 16)));
    }
    float2 fA0 = __half22float2(aA[0]), fA1 = __half22float2(aA[1]);
    float2 fA2 = __half22float2(aA[2]), fA3 = __half22float2(aA[3]);
    float2 fB0 = __half22float2(aB[0]), fB1 = __half22float2(aB[1]);
    float2 fB2 = __half22float2(aB[2]), fB3 = __half22float2(aB[3]);
    float s0 = (fA0.x + fA1.x) + (fA2.x + fA3.x);
    float s1 = (fA0.y + fA1.y) + (fA2.y + fA3.y);
    float s2 = (fB0.x + fB1.x) + (fB2.x + fB3.x);
    float s3 = (fB0.y + fB1.y) + (fB2.y + fB3.y);

    float d = g_dinv[n];
    float4 b = __ldg(((const float4*)bias) + lane);
    float o0 = fmaxf(fmaf(d, s0, b.x), 0.f);
    float o1 = fmaxf(fmaf(d, s1, b.y), 0.f);
    float o2 = fmaxf(fmaf(d, s2, b.z), 0.f);
    float o3 = fmaxf(fmaf(d, s3, b.w), 0.f);

    if (!last) {
        __nv_bfloat162 p0 = __floats2bfloat162_rn(o0, o1);
        __nv_bfloat162 p1 = __floats2bfloat162_rn(o2, o3);
        uint2 o; o.x = *(unsigned*)&p0; o.y = *(unsigned*)&p1;
        ((uint2*)g_hb)[(size_t)n * 32 + lane] = o;
    } else {
        float* dst = g_pool + g_batch[n] * H + lane * 4;
        asm volatile("red.global.add.v4.f32 [%0], {%1,%2,%3,%4};"
                     :: "l"(dst), "f"(o0), "f"(o1), "f"(o2), "f"(o3) : "memory");
    }
}

// ---------------- classifier + re-zero tail ----------------
__global__ void k_classifier(const float* __restrict__ Wc1, const float* __restrict__ bc1,
                             const float* __restrict__ Wc2, const float* __restrict__ bc2,
                             float* __restrict__ out) {
    __shared__ float gs[128];
    __shared__ float zs[64];
    int b = blockIdx.x, t = threadIdx.x;
    float cnt = fmaxf((float)g_cnt[b], 1.f);
    gs[t] = g_pool[b * H + t] / cnt;
    __syncthreads();
    if (t < 64) {
        float z = bc1[t];
#pragma unroll 4
        for (int k = 0; k < 128; k++) z = fmaf(gs[k], Wc1[k * 64 + t], z);
        z = fmaxf(z, 0.f);
        zs[t] = z * Wc2[t];
    }
    __syncthreads();
    if (t == 0) {
        float s = bc2[0];
#pragma unroll
        for (int k = 0; k < 64; k++) s += zs[k];
        out[b] = 1.f / (1.f + expf(-s));
    }
    // restore zero-invariant for next replay
    g_pool[b * H + t] = 0.f;
    if (t == 0) g_cnt[b] = 0;
    for (int i = b * 128 + t; i < NN; i += NG * 128) g_deg[i] = 0;
}

// ---------------- launch ----------------
extern "C" void kernel_launch(void* const* d_in, const int* in_sizes, int n_in,
                              void* d_out, int out_size) {
    const float* x     = (const float*)d_in[0];
    const void*  ei    = d_in[1];
    const void*  batch = d_in[2];
    const float* W_emb = (const float*)d_in[3];
    const float* b_emb = (const float*)d_in[4];
    const float* W_gnn = (const float*)d_in[5];
    const float* b_gnn = (const float*)d_in[6];
    const float* W_c1  = (const float*)d_in[7];
    const float* b_c1  = (const float*)d_in[8];
    const float* W_c2  = (const float*)d_in[9];
    const float* b_c2  = (const float*)d_in[10];
    float* out = (float*)d_out;

    const int GEMM_SMEM = (128 * AST + 128 * 64) * 4;   // 67584 B
    cudaFuncSetAttribute(k_gemm, cudaFuncAttributeMaxDynamicSharedMemorySize, GEMM_SMEM);
    const int NSCAN = (NN + 1023) / 1024;

    k_conv_edges<<<NE / 4 / 256, 256>>>(ei);              // 0
    k_scan1<<<NSCAN, 1024>>>();                           // 1
    k_scan3<<<NSCAN, 1024>>>();                           // 2
    k_scatter<<<NE / 4 / 256, 256>>>(ei);                 // 3  <- ncu window
    k_conv_batch<<<(NN / 4 + 255) / 256, 256>>>(batch, ei);
    k_uv<<<1, 128>>>(W_emb, b_emb, W_gnn);

    // layer 0 (rank-1 collapse)
    k_m0<<<NN * 32 / 256, 256>>>(x);
    k_agg<<<NN * 32 / 256, 256>>>(b_gnn, 0);

    // layers 1..2
    for (int l = 1; l < 3; l++) {
        k_gemm<<<NN_PAD / 128, 256, GEMM_SMEM>>>(W_gnn + (size_t)l * H * H);
        k_agg<<<NN * 32 / 256, 256>>>(b_gnn + l * H, l == 2);
    }

    k_classifier<<<NG, 128>>>(W_c1, b_c1, W_c2, b_c2, out);
}

// round 9
// speedup vs baseline: 1.0791x; 1.0791x over previous
#include <cuda_runtime.h>
#include <cuda_bf16.h>
#include <cuda_fp16.h>
#include <math.h>

#define NN 100000
#define NN_PAD 100096            // 782 * 128
#define NE 3200000
#define NG 128
#define H  128

// ---------------- scratch (device globals; zero-initialized, no allocation) -----
__device__ int      g_csr[NE];
__device__ int      g_off[NN + 1];
__device__ int      g_cur[NN];
__device__ int      g_deg[NN];          // zero at entry (module-load / classifier tail)
__device__ int      g_bsum[128];
__device__ int      g_batch[NN];
__device__ int      g_cnt[NG];          // zero at entry
__device__ float    g_dinv[NN_PAD];     // pad rows stay 0
__device__ unsigned g_hb[(size_t)NN_PAD * 64];   // h in bf16 (64 uints = 128 bf16/row)
__device__ unsigned g_m8[(size_t)NN_PAD * 32];   // m in fp8 e4m3 (32 uints = 128 fp8/row)
__device__ uint2    g_wp[2][128 * 32];  // pre-packed bf16 B operands (layers 1,2)
__device__ float    g_pool[NG * H];     // zero at entry
__device__ float    g_u[H];
__device__ float    g_v[H];

// Deterministic dtype probe: 4 leading values read as int64 all being valid node
// ids implies int64 layout.
__device__ __forceinline__ bool idx_is64(const void* p) {
    const long long* q = (const long long*)p;
    bool ok = true;
#pragma unroll
    for (int i = 0; i < 4; i++) {
        long long v = q[i];
        if (v < 0 || v >= NN) ok = false;
    }
    return ok;
}

// ---------------- fp8 helpers ----------------
__device__ __forceinline__ __half2 fp8x2_to_h2(unsigned short s) {
    unsigned r;
    asm("cvt.rn.f16x2.e4m3x2 %0, %1;" : "=r"(r) : "h"(s));
    return *(__half2*)&r;
}
__device__ __forceinline__ unsigned short f2_to_fp8x2(float lo, float hi) {
    unsigned short r;
    asm("cvt.rn.satfinite.e4m3x2.f32 %0, %1, %2;" : "=h"(r) : "f"(hi), "f"(lo));
    return r;
}
__device__ __forceinline__ unsigned pack4_fp8(float f0, float f1, float f2, float f3) {
    unsigned lo = f2_to_fp8x2(f0, f1);
    unsigned hi = f2_to_fp8x2(f2, f3);
    return lo | (hi << 16);
}

// ---------------- preprocessing (R6 structure: RED histogram, atomic scatter) ---
__global__ void k_conv_edges(const void* ei) {
    bool is64 = idx_is64(ei);
    int e = blockIdx.x * blockDim.x + threadIdx.x;   // NE threads exactly
    int c = is64 ? (int)__ldg(((const long long*)ei) + NE + e)
                 : __ldg(((const int*)ei) + NE + e);
    atomicAdd(&g_deg[c], 1);                          // no return use -> RED
}

__global__ void k_conv_batch(const void* b, const void* ei) {
    bool is64 = idx_is64(ei);
    int idx = blockIdx.x * blockDim.x + threadIdx.x;
    if (idx * 4 >= NN) return;
    int g0, g1, g2, g3;
    if (is64) {
        const longlong2* p = (const longlong2*)b;
        longlong2 a = __ldg(p + (size_t)idx * 2), c = __ldg(p + (size_t)idx * 2 + 1);
        g0 = (int)a.x; g1 = (int)a.y; g2 = (int)c.x; g3 = (int)c.y;
    } else {
        int4 a = __ldg(((const int4*)b) + idx);
        g0 = a.x; g1 = a.y; g2 = a.z; g3 = a.w;
    }
    ((int4*)g_batch)[idx] = make_int4(g0, g1, g2, g3);
    atomicAdd(&g_cnt[g0], 1);
    atomicAdd(&g_cnt[g1], 1);
    atomicAdd(&g_cnt[g2], 1);
    atomicAdd(&g_cnt[g3], 1);
}

__global__ void k_scan1() {
    __shared__ int s[1024];
    int t = threadIdx.x, gid = blockIdx.x * 1024 + t;
    int v = (gid < NN) ? g_deg[gid] : 0;
    s[t] = v; __syncthreads();
    for (int d = 1; d < 1024; d <<= 1) {
        int x = (t >= d) ? s[t - d] : 0;
        __syncthreads();
        s[t] += x; __syncthreads();
    }
    if (gid < NN) g_off[gid] = s[t] - v;
    if (t == 1023) g_bsum[blockIdx.x] = s[1023];
}

// adds block-prefix + fused dinv + g_cur init
__global__ void k_scan3() {
    __shared__ int s[128];
    int t = threadIdx.x, nb = blockIdx.x;
    if (t < 128) s[t] = (t < nb) ? g_bsum[t] : 0;
    __syncthreads();
    for (int d = 64; d > 0; d >>= 1) {
        if (t < d) s[t] += s[t + d];
        __syncthreads();
    }
    int base = s[0];
    int gid = nb * 1024 + t;
    if (gid < NN) {
        int o = g_off[gid] + base;
        g_off[gid] = o;
        g_cur[gid] = o;
        g_dinv[gid] = rsqrtf((float)(1 + g_deg[gid]));
    }
    if (nb == 0 && t == 0) g_off[NN] = NE;
}

__global__ void k_scatter(const void* ei) {
    bool is64 = idx_is64(ei);
    int e = blockIdx.x * blockDim.x + threadIdx.x;   // NE threads exactly
    int r, c;
    if (is64) {
        const long long* p = (const long long*)ei;
        r = (int)__ldg(p + e); c = (int)__ldg(p + NE + e);
    } else {
        const int* p = (const int*)ei;
        r = __ldg(p + e); c = __ldg(p + NE + e);
    }
    int pos = atomicAdd(&g_cur[c], 1);
    g_csr[pos] = r;
}

// u = W_emb @ W0, v = b_emb @ W0
__global__ void k_uv(const float* __restrict__ We, const float* __restrict__ be,
                     const float* __restrict__ W0) {
    int j = threadIdx.x;
    float u = 0.f, v = 0.f;
#pragma unroll 4
    for (int k = 0; k < 128; k++) {
        float w = W0[k * 128 + j];
        u = fmaf(We[k], w, u);
        v = fmaf(be[k], w, v);
    }
    g_u[j] = u; g_v[j] = v;
}

// one-time pack of W (layers 1,2) into the GEMM's swizzled bf16 B layout
__global__ void k_wpack(const float* __restrict__ W_gnn) {
    int l = blockIdx.x;                               // 0 -> layer1, 1 -> layer2
    const float* Wl = W_gnn + (size_t)(l + 1) * H * H;
    for (int idx = threadIdx.x; idx < 32 * 128; idx += blockDim.x) {
        int j = idx >> 7, n = idx & 127;
        int ks = j >> 2, tt = j & 3;
        int kp0 = ks * 8 + tt, kp1 = kp0 + 4;
        __nv_bfloat162 p0 = __floats2bfloat162_rn(Wl[(2 * kp0) * 128 + n],
                                                  Wl[(2 * kp0 + 1) * 128 + n]);
        __nv_bfloat162 p1 = __floats2bfloat162_rn(Wl[(2 * kp1) * 128 + n],
                                                  Wl[(2 * kp1 + 1) * 128 + n]);
        uint2 o; o.x = *(unsigned*)&p0; o.y = *(unsigned*)&p1;
        g_wp[l][n * 32 + ((j + 4 * (n & 3)) & 31)] = o;
    }
}

// m0[n] = dinv[n] * (x[n]*u + v), stored fp8
__global__ void k_m0(const float* __restrict__ x) {
    int i = blockIdx.x * blockDim.x + threadIdx.x;   // NN*32 threads
    int n = i >> 5, j4 = i & 31;
    float xv = __ldg(&x[n]);
    float d = g_dinv[n];
    float4 u = ((const float4*)g_u)[j4];
    float4 v = ((const float4*)g_v)[j4];
    g_m8[(size_t)n * 32 + j4] = pack4_fp8(
        d * fmaf(xv, u.x, v.x), d * fmaf(xv, u.y, v.y),
        d * fmaf(xv, u.z, v.z), d * fmaf(xv, u.w, v.w));
}

// ---------------- bf16 tensor-core GEMM: m = dinv ⊙ (h @ W), fp8 out ----------
#define AST 68
__global__ void __launch_bounds__(256, 2) k_gemm(const uint2* __restrict__ Wp) {
    extern __shared__ unsigned smem_u[];
    unsigned* hs  = smem_u;                          // 128*68 uints
    uint2*    WtP = (uint2*)(smem_u + 128 * AST);    // 128*32 uint2
    int t = threadIdx.x;
    int row0 = blockIdx.x * 128;

    // stage h (straight bf16 copy)
    {
        const uint4* src = (const uint4*)(g_hb + (size_t)row0 * 64);
        for (int idx = t; idx < 128 * 16; idx += 256) {
            int r = idx >> 4, c = idx & 15;
            *(uint4*)(hs + r * AST + c * 4) = src[r * 16 + c];
        }
    }
    // stage pre-packed W (straight copy)
    {
        uint4* dst = (uint4*)WtP;
        const uint4* s4 = (const uint4*)Wp;
        for (int i = t; i < 2048; i += 256) dst[i] = __ldg(s4 + i);
    }
    __syncthreads();

    int w = t >> 5, lane = t & 31, g = lane >> 2, tt = lane & 3;
    int wr = w * 16;

    float c[16][4];
#pragma unroll
    for (int nt = 0; nt < 16; nt++)
        c[nt][0] = c[nt][1] = c[nt][2] = c[nt][3] = 0.f;

#pragma unroll
    for (int ks = 0; ks < 8; ks++) {
        int kb = ks * 8;
        unsigned a0 = hs[(wr + g) * AST + kb + tt];
        unsigned a1 = hs[(wr + g + 8) * AST + kb + tt];
        unsigned a2 = hs[(wr + g) * AST + kb + tt + 4];
        unsigned a3 = hs[(wr + g + 8) * AST + kb + tt + 4];
#pragma unroll
        for (int nt = 0; nt < 16; nt++) {
            int n = nt * 8 + g;
            uint2 b01 = WtP[n * 32 + (((ks * 4 + tt) + 4 * (n & 3)) & 31)];
            asm volatile(
                "mma.sync.aligned.m16n8k16.row.col.f32.bf16.bf16.f32 "
                "{%0,%1,%2,%3}, {%4,%5,%6,%7}, {%8,%9}, {%0,%1,%2,%3};"
                : "+f"(c[nt][0]), "+f"(c[nt][1]), "+f"(c[nt][2]), "+f"(c[nt][3])
                : "r"(a0), "r"(a1), "r"(a2), "r"(a3), "r"(b01.x), "r"(b01.y));
        }
    }

    int r0 = row0 + wr + g, r1 = r0 + 8;
    float d0 = g_dinv[r0], d1 = g_dinv[r1];
    unsigned short* m8s = (unsigned short*)g_m8;     // row = 64 ushorts
#pragma unroll
    for (int nt = 0; nt < 16; nt++) {
        int colp = nt * 4 + tt;
        m8s[(size_t)r0 * 64 + colp] = f2_to_fp8x2(c[nt][0] * d0, c[nt][1] * d0);
        m8s[(size_t)r1 * 64 + colp] = f2_to_fp8x2(c[nt][2] * d1, c[nt][3] * d1);
    }
}

// ---------------- aggregation: warp per node, fp8 gathers, 8-wide MLP ----------
__device__ __forceinline__ unsigned ldcg_u(const unsigned* p) { return __ldcg(p); }

__global__ void k_agg(const float* __restrict__ bias, int last) {
    unsigned n = (blockIdx.x * blockDim.x + threadIdx.x) >> 5;
    if (n >= NN) return;
    int lane = threadIdx.x & 31;
    const unsigned* m8 = g_m8;                       // row = 32 uints = 128 fp8
    __half2 aA[4], aB[4];
#pragma unroll
    for (int j = 0; j < 4; j++) { aA[j] = __half2half2(__ushort_as_half(0)); aB[j] = aA[j]; }
    {
        unsigned v = ldcg_u(m8 + (size_t)n * 32 + lane);   // self-loop
        aA[0] = fp8x2_to_h2((unsigned short)v);
        aB[0] = fp8x2_to_h2((unsigned short)(v >> 16));
    }
    int s = g_off[n], e = g_off[n + 1];
    int i = s;
    for (; i + 8 <= e; i += 8) {
        int r0 = __ldcs(g_csr + i),     r1 = __ldcs(g_csr + i + 1);
        int r2 = __ldcs(g_csr + i + 2), r3 = __ldcs(g_csr + i + 3);
        int r4 = __ldcs(g_csr + i + 4), r5 = __ldcs(g_csr + i + 5);
        int r6 = __ldcs(g_csr + i + 6), r7 = __ldcs(g_csr + i + 7);
        unsigned v0 = ldcg_u(m8 + (size_t)r0 * 32 + lane);
        unsigned v1 = ldcg_u(m8 + (size_t)r1 * 32 + lane);
        unsigned v2 = ldcg_u(m8 + (size_t)r2 * 32 + lane);
        unsigned v3 = ldcg_u(m8 + (size_t)r3 * 32 + lane);
        unsigned v4 = ldcg_u(m8 + (size_t)r4 * 32 + lane);
        unsigned v5 = ldcg_u(m8 + (size_t)r5 * 32 + lane);
        unsigned v6 = ldcg_u(m8 + (size_t)r6 * 32 + lane);
        unsigned v7 = ldcg_u(m8 + (size_t)r7 * 32 + lane);
        aA[0] = __hadd2(aA[0], fp8x2_to_h2((unsigned short)v0));
        aB[0] = __hadd2(aB[0], fp8x2_to_h2((unsigned short)(v0 >> 16)));
        aA[1] = __hadd2(aA[1], fp8x2_to_h2((unsigned short)v1));
        aB[1] = __hadd2(aB[1], fp8x2_to_h2((unsigned short)(v1 >> 16)));
        aA[2] = __hadd2(aA[2], fp8x2_to_h2((unsigned short)v2));
        aB[2] = __hadd2(aB[2], fp8x2_to_h2((unsigned short)(v2 >> 16)));
        aA[3] = __hadd2(aA[3], fp8x2_to_h2((unsigned short)v3));
        aB[3] = __hadd2(aB[3], fp8x2_to_h2((unsigned short)(v3 >> 16)));
        aA[0] = __hadd2(aA[0], fp8x2_to_h2((unsigned short)v4));
        aB[0] = __hadd2(aB[0], fp8x2_to_h2((unsigned short)(v4 >> 16)));
        aA[1] = __hadd2(aA[1], fp8x2_to_h2((unsigned short)v5));
        aB[1] = __hadd2(aB[1], fp8x2_to_h2((unsigned short)(v5 >> 16)));
        aA[2] = __hadd2(aA[2], fp8x2_to_h2((unsigned short)v6));
        aB[2] = __hadd2(aB[2], fp8x2_to_h2((unsigned short)(v6 >> 16)));
        aA[3] = __hadd2(aA[3], fp8x2_to_h2((unsigned short)v7));
        aB[3] = __hadd2(aB[3], fp8x2_to_h2((unsigned short)(v7 >> 16)));
    }
    for (; i < e; i++) {
        int r = __ldcs(g_csr + i);
        unsigned v = ldcg_u(m8 + (size_t)r * 32 + lane);
        aA[0] = __hadd2(aA[0], fp8x2_to_h2((unsigned short)v));
        aB[0] = __hadd2(aB[0], fp8x2_to_h2((unsigned short)(v >> 16)));
    }
    float2 fA0 = __half22float2(aA[0]), fA1 = __half22float2(aA[1]);
    float2 fA2 = __half22float2(aA[2]), fA3 = __half22float2(aA[3]);
    float2 fB0 = __half22float2(aB[0]), fB1 = __half22float2(aB[1]);
    float2 fB2 = __half22float2(aB[2]), fB3 = __half22float2(aB[3]);
    float s0 = (fA0.x + fA1.x) + (fA2.x + fA3.x);
    float s1 = (fA0.y + fA1.y) + (fA2.y + fA3.y);
    float s2 = (fB0.x + fB1.x) + (fB2.x + fB3.x);
    float s3 = (fB0.y + fB1.y) + (fB2.y + fB3.y);

    float d = g_dinv[n];
    float4 b = __ldg(((const float4*)bias) + lane);
    float o0 = fmaxf(fmaf(d, s0, b.x), 0.f);
    float o1 = fmaxf(fmaf(d, s1, b.y), 0.f);
    float o2 = fmaxf(fmaf(d, s2, b.z), 0.f);
    float o3 = fmaxf(fmaf(d, s3, b.w), 0.f);

    if (!last) {
        __nv_bfloat162 p0 = __floats2bfloat162_rn(o0, o1);
        __nv_bfloat162 p1 = __floats2bfloat162_rn(o2, o3);
        uint2 o; o.x = *(unsigned*)&p0; o.y = *(unsigned*)&p1;
        ((uint2*)g_hb)[(size_t)n * 32 + lane] = o;
    } else {
        float* dst = g_pool + g_batch[n] * H + lane * 4;
        asm volatile("red.global.add.v4.f32 [%0], {%1,%2,%3,%4};"
                     :: "l"(dst), "f"(o0), "f"(o1), "f"(o2), "f"(o3) : "memory");
    }
}

// ---------------- classifier + re-zero tail ----------------
__global__ void k_classifier(const float* __restrict__ Wc1, const float* __restrict__ bc1,
                             const float* __restrict__ Wc2, const float* __restrict__ bc2,
                             float* __restrict__ out) {
    __shared__ float gs[128];
    __shared__ float zs[64];
    int b = blockIdx.x, t = threadIdx.x;
    float cnt = fmaxf((float)g_cnt[b], 1.f);
    gs[t] = g_pool[b * H + t] / cnt;
    __syncthreads();
    if (t < 64) {
        float z = bc1[t];
#pragma unroll 4
        for (int k = 0; k < 128; k++) z = fmaf(gs[k], Wc1[k * 64 + t], z);
        z = fmaxf(z, 0.f);
        zs[t] = z * Wc2[t];
    }
    __syncthreads();
    if (t == 0) {
        float s = bc2[0];
#pragma unroll
        for (int k = 0; k < 64; k++) s += zs[k];
        out[b] = 1.f / (1.f + expf(-s));
    }
    // restore zero-invariant for next replay
    g_pool[b * H + t] = 0.f;
    if (t == 0) g_cnt[b] = 0;
    for (int i = b * 128 + t; i < NN; i += NG * 128) g_deg[i] = 0;
}

// ---------------- launch ----------------
extern "C" void kernel_launch(void* const* d_in, const int* in_sizes, int n_in,
                              void* d_out, int out_size) {
    const float* x     = (const float*)d_in[0];
    const void*  ei    = d_in[1];
    const void*  batch = d_in[2];
    const float* W_emb = (const float*)d_in[3];
    const float* b_emb = (const float*)d_in[4];
    const float* W_gnn = (const float*)d_in[5];
    const float* b_gnn = (const float*)d_in[6];
    const float* W_c1  = (const float*)d_in[7];
    const float* b_c1  = (const float*)d_in[8];
    const float* W_c2  = (const float*)d_in[9];
    const float* b_c2  = (const float*)d_in[10];
    float* out = (float*)d_out;

    const int GEMM_SMEM = (128 * AST + 128 * 64) * 4;   // 67584 B
    cudaFuncSetAttribute(k_gemm, cudaFuncAttributeMaxDynamicSharedMemorySize, GEMM_SMEM);
    const int NSCAN = (NN + 1023) / 1024;

    k_conv_edges<<<NE / 256, 256>>>(ei);                  // 0
    k_scan1<<<NSCAN, 1024>>>();                           // 1
    k_scan3<<<NSCAN, 1024>>>();                           // 2
    k_scatter<<<NE / 256, 256>>>(ei);                     // 3  <- ncu window
    k_conv_batch<<<(NN / 4 + 255) / 256, 256>>>(batch, ei);
    k_uv<<<1, 128>>>(W_emb, b_emb, W_gnn);
    k_wpack<<<2, 256>>>(W_gnn);

    // layer 0 (rank-1 collapse)
    k_m0<<<NN * 32 / 256, 256>>>(x);
    k_agg<<<NN * 32 / 256, 256>>>(b_gnn, 0);

    // layers 1..2 (device-resident packed W)
    uint2* wp0;  cudaGetSymbolAddress((void**)&wp0, g_wp);
    for (int l = 1; l < 3; l++) {
        k_gemm<<<NN_PAD / 128, 256, GEMM_SMEM>>>(wp0 + (size_t)(l - 1) * 128 * 32);
        k_agg<<<NN * 32 / 256, 256>>>(b_gnn + l * H, l == 2);
    }

    k_classifier<<<NG, 128>>>(W_c1, b_c1, W_c2, b_c2, out);
}

// round 10
// speedup vs baseline: 1.1295x; 1.0467x over previous
#include <cuda_runtime.h>
#include <cuda_bf16.h>
#include <cuda_fp16.h>
#include <math.h>

#define NN 100000
#define NN_PAD 100096            // 782 * 128
#define NE 3200000
#define NG 128
#define H  128

// ---------------- scratch (device globals; zero-initialized, no allocation) -----
__device__ int      g_csr[NE];
__device__ int      g_off[NN + 1];
__device__ int      g_cur[NN];
__device__ int      g_deg[NN];          // zero at entry (module-load / classifier tail)
__device__ int      g_bsum[128];
__device__ int      g_batch[NN];
__device__ int      g_cnt[NG];          // zero at entry
__device__ float    g_dinv[NN_PAD];     // pad rows stay 0
__device__ float2   g_yz[NN];           // (dinv*x, dinv) per node
__device__ unsigned g_hb[(size_t)NN_PAD * 64];   // h in bf16 (64 uints = 128 bf16/row)
__device__ unsigned g_m8[(size_t)NN_PAD * 32];   // m in fp8 e4m3 (32 uints = 128 fp8/row)
__device__ uint2    g_wp[2][128 * 32];  // pre-packed bf16 B operands (layers 1,2)
__device__ float    g_pool[NG * H];     // zero at entry
__device__ float    g_u[H];
__device__ float    g_v[H];

// Deterministic dtype probe: 4 leading values read as int64 all being valid node
// ids implies int64 layout.
__device__ __forceinline__ bool idx_is64(const void* p) {
    const long long* q = (const long long*)p;
    bool ok = true;
#pragma unroll
    for (int i = 0; i < 4; i++) {
        long long v = q[i];
        if (v < 0 || v >= NN) ok = false;
    }
    return ok;
}

// ---------------- fp8 helpers ----------------
__device__ __forceinline__ __half2 fp8x2_to_h2(unsigned short s) {
    unsigned r;
    asm("cvt.rn.f16x2.e4m3x2 %0, %1;" : "=r"(r) : "h"(s));
    return *(__half2*)&r;
}
__device__ __forceinline__ unsigned short f2_to_fp8x2(float lo, float hi) {
    unsigned short r;
    asm("cvt.rn.satfinite.e4m3x2.f32 %0, %1, %2;" : "=h"(r) : "f"(hi), "f"(lo));
    return r;
}

// ---------------- preprocessing (RED histogram, atomic scatter) ----------------
__global__ void k_conv_edges(const void* ei) {
    bool is64 = idx_is64(ei);
    int e = blockIdx.x * blockDim.x + threadIdx.x;   // NE threads exactly
    int c = is64 ? (int)__ldg(((const long long*)ei) + NE + e)
                 : __ldg(((const int*)ei) + NE + e);
    atomicAdd(&g_deg[c], 1);                          // no return use -> RED
}

__global__ void k_conv_batch(const void* b, const void* ei) {
    bool is64 = idx_is64(ei);
    int idx = blockIdx.x * blockDim.x + threadIdx.x;
    if (idx * 4 >= NN) return;
    int g0, g1, g2, g3;
    if (is64) {
        const longlong2* p = (const longlong2*)b;
        longlong2 a = __ldg(p + (size_t)idx * 2), c = __ldg(p + (size_t)idx * 2 + 1);
        g0 = (int)a.x; g1 = (int)a.y; g2 = (int)c.x; g3 = (int)c.y;
    } else {
        int4 a = __ldg(((const int4*)b) + idx);
        g0 = a.x; g1 = a.y; g2 = a.z; g3 = a.w;
    }
    ((int4*)g_batch)[idx] = make_int4(g0, g1, g2, g3);
    atomicAdd(&g_cnt[g0], 1);
    atomicAdd(&g_cnt[g1], 1);
    atomicAdd(&g_cnt[g2], 1);
    atomicAdd(&g_cnt[g3], 1);
}

__global__ void k_scan1() {
    __shared__ int s[1024];
    int t = threadIdx.x, gid = blockIdx.x * 1024 + t;
    int v = (gid < NN) ? g_deg[gid] : 0;
    s[t] = v; __syncthreads();
    for (int d = 1; d < 1024; d <<= 1) {
        int x = (t >= d) ? s[t - d] : 0;
        __syncthreads();
        s[t] += x; __syncthreads();
    }
    if (gid < NN) g_off[gid] = s[t] - v;
    if (t == 1023) g_bsum[blockIdx.x] = s[1023];
}

// block-prefix + dinv + (y,z) table
__global__ void k_scan3(const float* __restrict__ x) {
    __shared__ int s[128];
    int t = threadIdx.x, nb = blockIdx.x;
    if (t < 128) s[t] = (t < nb) ? g_bsum[t] : 0;
    __syncthreads();
    for (int d = 64; d > 0; d >>= 1) {
        if (t < d) s[t] += s[t + d];
        __syncthreads();
    }
    int base = s[0];
    int gid = nb * 1024 + t;
    if (gid < NN) {
        int o = g_off[gid] + base;
        g_off[gid] = o;
        g_cur[gid] = o;
        float d = rsqrtf((float)(1 + g_deg[gid]));
        g_dinv[gid] = d;
        g_yz[gid] = make_float2(d * __ldg(&x[gid]), d);
    }
    if (nb == 0 && t == 0) g_off[NN] = NE;
}

__global__ void k_scatter(const void* ei) {
    bool is64 = idx_is64(ei);
    int e = blockIdx.x * blockDim.x + threadIdx.x;   // NE threads exactly
    int r, c;
    if (is64) {
        const long long* p = (const long long*)ei;
        r = (int)__ldg(p + e); c = (int)__ldg(p + NE + e);
    } else {
        const int* p = (const int*)ei;
        r = __ldg(p + e); c = __ldg(p + NE + e);
    }
    int pos = atomicAdd(&g_cur[c], 1);
    g_csr[pos] = r;
}

// blocks 0,1: pack W layers 1,2 into swizzled bf16 B layout; block 2: u,v
__global__ void k_wpack(const float* __restrict__ W_gnn,
                        const float* __restrict__ We, const float* __restrict__ be) {
    int l = blockIdx.x;
    if (l < 2) {
        const float* Wl = W_gnn + (size_t)(l + 1) * H * H;
        for (int idx = threadIdx.x; idx < 32 * 128; idx += blockDim.x) {
            int j = idx >> 7, n = idx & 127;
            int ks = j >> 2, tt = j & 3;
            int kp0 = ks * 8 + tt, kp1 = kp0 + 4;
            __nv_bfloat162 p0 = __floats2bfloat162_rn(Wl[(2 * kp0) * 128 + n],
                                                      Wl[(2 * kp0 + 1) * 128 + n]);
            __nv_bfloat162 p1 = __floats2bfloat162_rn(Wl[(2 * kp1) * 128 + n],
                                                      Wl[(2 * kp1 + 1) * 128 + n]);
            uint2 o; o.x = *(unsigned*)&p0; o.y = *(unsigned*)&p1;
            g_wp[l][n * 32 + ((j + 4 * (n & 3)) & 31)] = o;
        }
    } else if (threadIdx.x < 128) {
        int j = threadIdx.x;
        float u = 0.f, v = 0.f;
#pragma unroll 4
        for (int k = 0; k < 128; k++) {
            float w = W_gnn[k * 128 + j];            // layer 0
            u = fmaf(We[k], w, u);
            v = fmaf(be[k], w, v);
        }
        g_u[j] = u; g_v[j] = v;
    }
}

// ---------------- layer 0: scalar aggregation (rank-1 collapse), h1 out bf16 ----
__global__ void k_agg0(const float* __restrict__ bias) {
    unsigned n = (blockIdx.x * blockDim.x + threadIdx.x) >> 5;
    if (n >= NN) return;
    int lane = threadIdx.x & 31;
    int s = g_off[n], e = g_off[n + 1];
    float A = 0.f, B = 0.f;
    for (int i = s + lane; i < e; i += 32) {
        int r = __ldcs(g_csr + i);                   // warp-coalesced
        float2 yz = __ldg(&g_yz[r]);                 // 8B random gather (L2)
        A += yz.x; B += yz.y;
    }
#pragma unroll
    for (int o = 16; o > 0; o >>= 1) {
        A += __shfl_xor_sync(0xffffffffu, A, o);
        B += __shfl_xor_sync(0xffffffffu, B, o);
    }
    float2 self = __ldg(&g_yz[n]);                   // self-loop term
    A += self.x; B += self.y;
    float d = g_dinv[n];
    float4 u = ((const float4*)g_u)[lane];
    float4 v = ((const float4*)g_v)[lane];
    float4 b = __ldg(((const float4*)bias) + lane);
    float o0 = fmaxf(fmaf(d, fmaf(A, u.x, B * v.x), b.x), 0.f);
    float o1 = fmaxf(fmaf(d, fmaf(A, u.y, B * v.y), b.y), 0.f);
    float o2 = fmaxf(fmaf(d, fmaf(A, u.z, B * v.z), b.z), 0.f);
    float o3 = fmaxf(fmaf(d, fmaf(A, u.w, B * v.w), b.w), 0.f);
    __nv_bfloat162 p0 = __floats2bfloat162_rn(o0, o1);
    __nv_bfloat162 p1 = __floats2bfloat162_rn(o2, o3);
    uint2 o; o.x = *(unsigned*)&p0; o.y = *(unsigned*)&p1;
    ((uint2*)g_hb)[(size_t)n * 32 + lane] = o;
}

// ---------------- bf16 tensor-core GEMM: m = dinv ⊙ (h @ W), fp8 out ----------
#define AST 68
__global__ void __launch_bounds__(256, 2) k_gemm(const uint2* __restrict__ Wp) {
    extern __shared__ unsigned smem_u[];
    unsigned* hs  = smem_u;                          // 128*68 uints
    uint2*    WtP = (uint2*)(smem_u + 128 * AST);    // 128*32 uint2
    int t = threadIdx.x;
    int row0 = blockIdx.x * 128;

    {
        const uint4* src = (const uint4*)(g_hb + (size_t)row0 * 64);
        for (int idx = t; idx < 128 * 16; idx += 256) {
            int r = idx >> 4, c = idx & 15;
            *(uint4*)(hs + r * AST + c * 4) = src[r * 16 + c];
        }
    }
    {
        uint4* dst = (uint4*)WtP;
        const uint4* s4 = (const uint4*)Wp;
        for (int i = t; i < 2048; i += 256) dst[i] = __ldg(s4 + i);
    }
    __syncthreads();

    int w = t >> 5, lane = t & 31, g = lane >> 2, tt = lane & 3;
    int wr = w * 16;

    float c[16][4];
#pragma unroll
    for (int nt = 0; nt < 16; nt++)
        c[nt][0] = c[nt][1] = c[nt][2] = c[nt][3] = 0.f;

#pragma unroll
    for (int ks = 0; ks < 8; ks++) {
        int kb = ks * 8;
        unsigned a0 = hs[(wr + g) * AST + kb + tt];
        unsigned a1 = hs[(wr + g + 8) * AST + kb + tt];
        unsigned a2 = hs[(wr + g) * AST + kb + tt + 4];
        unsigned a3 = hs[(wr + g + 8) * AST + kb + tt + 4];
#pragma unroll
        for (int nt = 0; nt < 16; nt++) {
            int n = nt * 8 + g;
            uint2 b01 = WtP[n * 32 + (((ks * 4 + tt) + 4 * (n & 3)) & 31)];
            asm volatile(
                "mma.sync.aligned.m16n8k16.row.col.f32.bf16.bf16.f32 "
                "{%0,%1,%2,%3}, {%4,%5,%6,%7}, {%8,%9}, {%0,%1,%2,%3};"
                : "+f"(c[nt][0]), "+f"(c[nt][1]), "+f"(c[nt][2]), "+f"(c[nt][3])
                : "r"(a0), "r"(a1), "r"(a2), "r"(a3), "r"(b01.x), "r"(b01.y));
        }
    }

    int r0 = row0 + wr + g, r1 = r0 + 8;
    float d0 = g_dinv[r0], d1 = g_dinv[r1];
    unsigned short* m8s = (unsigned short*)g_m8;     // row = 64 ushorts
#pragma unroll
    for (int nt = 0; nt < 16; nt++) {
        int colp = nt * 4 + tt;
        m8s[(size_t)r0 * 64 + colp] = f2_to_fp8x2(c[nt][0] * d0, c[nt][1] * d0);
        m8s[(size_t)r1 * 64 + colp] = f2_to_fp8x2(c[nt][2] * d1, c[nt][3] * d1);
    }
}

// ---------------- aggregation (layers 1,2): warp/node, fp8 gathers, 8-wide MLP --
__device__ __forceinline__ unsigned ldcg_u(const unsigned* p) { return __ldcg(p); }

__global__ void k_agg(const float* __restrict__ bias, int last) {
    unsigned n = (blockIdx.x * blockDim.x + threadIdx.x) >> 5;
    if (n >= NN) return;
    int lane = threadIdx.x & 31;
    const unsigned* m8 = g_m8;                       // row = 32 uints = 128 fp8
    __half2 aA[4], aB[4];
#pragma unroll
    for (int j = 0; j < 4; j++) { aA[j] = __half2half2(__ushort_as_half(0)); aB[j] = aA[j]; }
    {
        unsigned v = ldcg_u(m8 + (size_t)n * 32 + lane);   // self-loop
        aA[0] = fp8x2_to_h2((unsigned short)v);
        aB[0] = fp8x2_to_h2((unsigned short)(v >> 16));
    }
    int s = g_off[n], e = g_off[n + 1];
    int i = s;
    for (; i + 8 <= e; i += 8) {
        int r0 = __ldcs(g_csr + i),     r1 = __ldcs(g_csr + i + 1);
        int r2 = __ldcs(g_csr + i + 2), r3 = __ldcs(g_csr + i + 3);
        int r4 = __ldcs(g_csr + i + 4), r5 = __ldcs(g_csr + i + 5);
        int r6 = __ldcs(g_csr + i + 6), r7 = __ldcs(g_csr + i + 7);
        unsigned v0 = ldcg_u(m8 + (size_t)r0 * 32 + lane);
        unsigned v1 = ldcg_u(m8 + (size_t)r1 * 32 + lane);
        unsigned v2 = ldcg_u(m8 + (size_t)r2 * 32 + lane);
        unsigned v3 = ldcg_u(m8 + (size_t)r3 * 32 + lane);
        unsigned v4 = ldcg_u(m8 + (size_t)r4 * 32 + lane);
        unsigned v5 = ldcg_u(m8 + (size_t)r5 * 32 + lane);
        unsigned v6 = ldcg_u(m8 + (size_t)r6 * 32 + lane);
        unsigned v7 = ldcg_u(m8 + (size_t)r7 * 32 + lane);
        aA[0] = __hadd2(aA[0], fp8x2_to_h2((unsigned short)v0));
        aB[0] = __hadd2(aB[0], fp8x2_to_h2((unsigned short)(v0 >> 16)));
        aA[1] = __hadd2(aA[1], fp8x2_to_h2((unsigned short)v1));
        aB[1] = __hadd2(aB[1], fp8x2_to_h2((unsigned short)(v1 >> 16)));
        aA[2] = __hadd2(aA[2], fp8x2_to_h2((unsigned short)v2));
        aB[2] = __hadd2(aB[2], fp8x2_to_h2((unsigned short)(v2 >> 16)));
        aA[3] = __hadd2(aA[3], fp8x2_to_h2((unsigned short)v3));
        aB[3] = __hadd2(aB[3], fp8x2_to_h2((unsigned short)(v3 >> 16)));
        aA[0] = __hadd2(aA[0], fp8x2_to_h2((unsigned short)v4));
        aB[0] = __hadd2(aB[0], fp8x2_to_h2((unsigned short)(v4 >> 16)));
        aA[1] = __hadd2(aA[1], fp8x2_to_h2((unsigned short)v5));
        aB[1] = __hadd2(aB[1], fp8x2_to_h2((unsigned short)(v5 >> 16)));
        aA[2] = __hadd2(aA[2], fp8x2_to_h2((unsigned short)v6));
        aB[2] = __hadd2(aB[2], fp8x2_to_h2((unsigned short)(v6 >> 16)));
        aA[3] = __hadd2(aA[3], fp8x2_to_h2((unsigned short)v7));
        aB[3] = __hadd2(aB[3], fp8x2_to_h2((unsigned short)(v7 >> 16)));
    }
    for (; i < e; i++) {
        int r = __ldcs(g_csr + i);
        unsigned v = ldcg_u(m8 + (size_t)r * 32 + lane);
        aA[0] = __hadd2(aA[0], fp8x2_to_h2((unsigned short)v));
        aB[0] = __hadd2(aB[0], fp8x2_to_h2((unsigned short)(v >> 16)));
    }
    float2 fA0 = __half22float2(aA[0]), fA1 = __half22float2(aA[1]);
    float2 fA2 = __half22float2(aA[2]), fA3 = __half22float2(aA[3]);
    float2 fB0 = __half22float2(aB[0]), fB1 = __half22float2(aB[1]);
    float2 fB2 = __half22float2(aB[2]), fB3 = __half22float2(aB[3]);
    float s0 = (fA0.x + fA1.x) + (fA2.x + fA3.x);
    float s1 = (fA0.y + fA1.y) + (fA2.y + fA3.y);
    float s2 = (fB0.x + fB1.x) + (fB2.x + fB3.x);
    float s3 = (fB0.y + fB1.y) + (fB2.y + fB3.y);

    float d = g_dinv[n];
    float4 b = __ldg(((const float4*)bias) + lane);
    float o0 = fmaxf(fmaf(d, s0, b.x), 0.f);
    float o1 = fmaxf(fmaf(d, s1, b.y), 0.f);
    float o2 = fmaxf(fmaf(d, s2, b.z), 0.f);
    float o3 = fmaxf(fmaf(d, s3, b.w), 0.f);

    if (!last) {
        __nv_bfloat162 p0 = __floats2bfloat162_rn(o0, o1);
        __nv_bfloat162 p1 = __floats2bfloat162_rn(o2, o3);
        uint2 o; o.x = *(unsigned*)&p0; o.y = *(unsigned*)&p1;
        ((uint2*)g_hb)[(size_t)n * 32 + lane] = o;
    } else {
        float* dst = g_pool + g_batch[n] * H + lane * 4;
        asm volatile("red.global.add.v4.f32 [%0], {%1,%2,%3,%4};"
                     :: "l"(dst), "f"(o0), "f"(o1), "f"(o2), "f"(o3) : "memory");
    }
}

// ---------------- classifier + re-zero tail ----------------
__global__ void k_classifier(const float* __restrict__ Wc1, const float* __restrict__ bc1,
                             const float* __restrict__ Wc2, const float* __restrict__ bc2,
                             float* __restrict__ out) {
    __shared__ float gs[128];
    __shared__ float zs[64];
    int b = blockIdx.x, t = threadIdx.x;
    float cnt = fmaxf((float)g_cnt[b], 1.f);
    gs[t] = g_pool[b * H + t] / cnt;
    __syncthreads();
    if (t < 64) {
        float z = bc1[t];
#pragma unroll 4
        for (int k = 0; k < 128; k++) z = fmaf(gs[k], Wc1[k * 64 + t], z);
        z = fmaxf(z, 0.f);
        zs[t] = z * Wc2[t];
    }
    __syncthreads();
    if (t == 0) {
        float s = bc2[0];
#pragma unroll
        for (int k = 0; k < 64; k++) s += zs[k];
        out[b] = 1.f / (1.f + expf(-s));
    }
    // restore zero-invariant for next replay
    g_pool[b * H + t] = 0.f;
    if (t == 0) g_cnt[b] = 0;
    for (int i = b * 128 + t; i < NN; i += NG * 128) g_deg[i] = 0;
}

// ---------------- launch ----------------
extern "C" void kernel_launch(void* const* d_in, const int* in_sizes, int n_in,
                              void* d_out, int out_size) {
    const float* x     = (const float*)d_in[0];
    const void*  ei    = d_in[1];
    const void*  batch = d_in[2];
    const float* W_emb = (const float*)d_in[3];
    const float* b_emb = (const float*)d_in[4];
    const float* W_gnn = (const float*)d_in[5];
    const float* b_gnn = (const float*)d_in[6];
    const float* W_c1  = (const float*)d_in[7];
    const float* b_c1  = (const float*)d_in[8];
    const float* W_c2  = (const float*)d_in[9];
    const float* b_c2  = (const float*)d_in[10];
    float* out = (float*)d_out;

    const int GEMM_SMEM = (128 * AST + 128 * 64) * 4;   // 67584 B
    cudaFuncSetAttribute(k_gemm, cudaFuncAttributeMaxDynamicSharedMemorySize, GEMM_SMEM);
    const int NSCAN = (NN + 1023) / 1024;

    k_conv_edges<<<NE / 256, 256>>>(ei);                  // 0
    k_scan1<<<NSCAN, 1024>>>();                           // 1
    k_scan3<<<NSCAN, 1024>>>(x);                          // 2
    k_scatter<<<NE / 256, 256>>>(ei);                     // 3  <- ncu window
    k_conv_batch<<<(NN / 4 + 255) / 256, 256>>>(batch, ei);
    k_wpack<<<3, 256>>>(W_gnn, W_emb, b_emb);

    // layer 0: scalar aggregation (rank-1 collapse), writes h1 directly
    k_agg0<<<NN * 32 / 256, 256>>>(b_gnn);

    // layers 1..2
    uint2* wp0;  cudaGetSymbolAddress((void**)&wp0, g_wp);
    for (int l = 1; l < 3; l++) {
        k_gemm<<<NN_PAD / 128, 256, GEMM_SMEM>>>(wp0 + (size_t)(l - 1) * 128 * 32);
        k_agg<<<NN * 32 / 256, 256>>>(b_gnn + l * H, l == 2);
    }

    k_classifier<<<NG, 128>>>(W_c1, b_c1, W_c2, b_c2, out);
}